// round 14
// baseline (speedup 1.0000x reference)
#include <cuda_runtime.h>
#include <cuda_fp16.h>
#include <math.h>
#include <stdint.h>

// ---------------------------------------------------------------------------
// Problem constants
// ---------------------------------------------------------------------------
#define BATCH   64
#define SEQ     577
#define MTOK    (BATCH * SEQ)      // 36928
#define MPAD    36992              // 289 * 128
#define C_EMB   768
#define C_QKV   2304
#define C_HID   3072
#define NHEAD   12
#define HDIM    64

#define EPI_BIAS_RES  1
#define EPI_GELU_H    2
#define EPI_HALF      3

#define NSM 148

// ---------------------------------------------------------------------------
// Scratch (device globals)
// ---------------------------------------------------------------------------
__device__ __half g_qkvh[(size_t)MTOK * C_QKV];       // qkv proj, fp16 row-major
__device__ float  g_x1 [(size_t)MTOK * C_EMB];        // residual 1
// fp16 activations, chunked+swizzled: [K/64][MPAD rows][64 fp16 = 128B]
__device__ __half g_actA[(size_t)MPAD * C_EMB];
__device__ __half g_actB[(size_t)MPAD * C_HID];
// fp16 weights, transposed chunked+swizzled: [K/64][N][64 fp16]
__device__ __half g_w   [(size_t)C_HID * C_EMB];

// ---------------------------------------------------------------------------
// PTX helpers
// ---------------------------------------------------------------------------
__device__ __forceinline__ uint32_t cvta_s(const void* p) {
    uint32_t a;
    asm("{ .reg .u64 t; cvta.to.shared.u64 t, %1; cvt.u32.u64 %0, t; }"
        : "=r"(a) : "l"(p));
    return a;
}
__device__ __forceinline__ void mbar_init(uint32_t mbar, uint32_t cnt) {
    asm volatile("mbarrier.init.shared.b64 [%0], %1;" :: "r"(mbar), "r"(cnt) : "memory");
}
__device__ __forceinline__ void mbar_expect_tx(uint32_t mbar, uint32_t bytes) {
    asm volatile("mbarrier.arrive.expect_tx.shared.b64 _, [%0], %1;"
                 :: "r"(mbar), "r"(bytes) : "memory");
}
__device__ __forceinline__ void mbar_arrive(uint32_t mbar) {
    asm volatile("mbarrier.arrive.shared.b64 _, [%0];" :: "r"(mbar) : "memory");
}
__device__ __forceinline__ void mbar_wait(uint32_t mbar, uint32_t phase) {
    asm volatile(
        "{\n\t"
        ".reg .pred P1;\n\t"
        "WAIT_LOOP_%=:\n\t"
        "mbarrier.try_wait.parity.acquire.cta.shared::cta.b64 P1, [%0], %1, 0x989680;\n\t"
        "@P1 bra.uni WAIT_DONE_%=;\n\t"
        "bra.uni WAIT_LOOP_%=;\n\t"
        "WAIT_DONE_%=:\n\t"
        "}"
        :: "r"(mbar), "r"(phase) : "memory");
}
__device__ __forceinline__ void bulk_ldg(uint32_t dst, const void* src,
                                         uint32_t bytes, uint32_t mbar) {
    asm volatile(
        "cp.async.bulk.shared::cluster.global.mbarrier::complete_tx::bytes "
        "[%0], [%1], %2, [%3];"
        :: "r"(dst), "l"(src), "r"(bytes), "r"(mbar) : "memory");
}
__device__ __forceinline__ void cp16(uint32_t dst, const void* src, uint32_t srcsize) {
    asm volatile("cp.async.cg.shared.global [%0], [%1], 16, %2;"
                 :: "r"(dst), "l"(src), "r"(srcsize) : "memory");
}
__device__ __forceinline__ void cp_commit() {
    asm volatile("cp.async.commit_group;" ::: "memory");
}
__device__ __forceinline__ void cp_wait0() {
    asm volatile("cp.async.wait_group 0;" ::: "memory");
}
__device__ __forceinline__ void ldsm4(uint32_t* r, uint32_t addr) {
    asm volatile("ldmatrix.sync.aligned.m8n8.x4.shared.b16 {%0,%1,%2,%3}, [%4];"
                 : "=r"(r[0]), "=r"(r[1]), "=r"(r[2]), "=r"(r[3]) : "r"(addr));
}
__device__ __forceinline__ void ldsm4t(uint32_t* r, uint32_t addr) {
    asm volatile("ldmatrix.sync.aligned.m8n8.x4.trans.shared.b16 {%0,%1,%2,%3}, [%4];"
                 : "=r"(r[0]), "=r"(r[1]), "=r"(r[2]), "=r"(r[3]) : "r"(addr));
}
__device__ __forceinline__ void mma_f16(float* c, const uint32_t* a, const uint32_t* b) {
    asm volatile(
        "mma.sync.aligned.m16n8k16.row.col.f32.f16.f16.f32 "
        "{%0,%1,%2,%3},{%4,%5,%6,%7},{%8,%9},{%0,%1,%2,%3};"
        : "+f"(c[0]), "+f"(c[1]), "+f"(c[2]), "+f"(c[3])
        : "r"(a[0]), "r"(a[1]), "r"(a[2]), "r"(a[3]), "r"(b[0]), "r"(b[1]));
}

// ---------------------------------------------------------------------------
// Fused LayerNorm + fp16 convert: warp-per-row, 8 rows per block.
// ---------------------------------------------------------------------------
__global__ __launch_bounds__(256) void ln_f16_ker(const float* __restrict__ x,
                                                  const float* __restrict__ gamma,
                                                  const float* __restrict__ beta,
                                                  uint8_t* __restrict__ dst)
{
    const int lane = threadIdx.x & 31, w = threadIdx.x >> 5;
    const int row = blockIdx.x * 8 + w;
    const float* xr = x + (size_t)row * C_EMB;

    float v[24];
    float s = 0.f, s2 = 0.f;
    #pragma unroll
    for (int g = 0; g < 3; g++) {
        const float4* p = (const float4*)(xr + g * 256 + lane * 8);
        float4 a = p[0], b = p[1];
        v[g*8+0]=a.x; v[g*8+1]=a.y; v[g*8+2]=a.z; v[g*8+3]=a.w;
        v[g*8+4]=b.x; v[g*8+5]=b.y; v[g*8+6]=b.z; v[g*8+7]=b.w;
        #pragma unroll
        for (int i = 0; i < 8; i++) { s += v[g*8+i]; s2 += v[g*8+i]*v[g*8+i]; }
    }
    #pragma unroll
    for (int off = 16; off > 0; off >>= 1) {
        s  += __shfl_xor_sync(0xFFFFFFFFu, s,  off);
        s2 += __shfl_xor_sync(0xFFFFFFFFu, s2, off);
    }
    const float mean = s * (1.0f / C_EMB);
    const float rstd = rsqrtf(s2 * (1.0f / C_EMB) - mean * mean + 1e-5f);

    #pragma unroll
    for (int g = 0; g < 3; g++) {
        const int k = g * 256 + lane * 8;
        const float4* gp = (const float4*)(gamma + k);
        const float4* bp = (const float4*)(beta + k);
        float4 g0 = gp[0], g1 = gp[1], b0 = bp[0], b1 = bp[1];
        float gg[8] = {g0.x,g0.y,g0.z,g0.w,g1.x,g1.y,g1.z,g1.w};
        float bb[8] = {b0.x,b0.y,b0.z,b0.w,b1.x,b1.y,b1.z,b1.w};
        union { __half h[8]; uint4 u; } uo;
        #pragma unroll
        for (int i = 0; i < 8; i++)
            uo.h[i] = __float2half_rn((v[g*8+i] - mean) * rstd * gg[i] + bb[i]);
        size_t base = ((size_t)(k >> 6) * MPAD + row) * 128
                    + ((uint32_t)((k & 63) * 2) ^ (uint32_t)((row & 7) << 4));
        *(uint4*)(dst + base) = uo.u;
    }
}

// ---------------------------------------------------------------------------
// convT: fp32 weights [K,N] -> transposed fp16 chunked swizzled [K/64][N][64]
// ---------------------------------------------------------------------------
__global__ void convT_ker(const float* __restrict__ w,
                          uint8_t* __restrict__ dst, int K, int N)
{
    __shared__ float tile[32][33];
    const int n0 = blockIdx.x * 32, k0 = blockIdx.y * 32;
    const int tx = threadIdx.x, ty = threadIdx.y;
    for (int i = ty; i < 32; i += 4)
        tile[i][tx] = w[(size_t)(k0 + i) * N + n0 + tx];
    __syncthreads();
    const int n = n0 + tx;
    const int k = k0 + ty * 8;
    union { __half h[8]; uint4 u; } uo;
    #pragma unroll
    for (int i = 0; i < 8; i++)
        uo.h[i] = __float2half_rn(tile[ty * 8 + i][tx]);
    size_t base = ((size_t)(k >> 6) * N + n) * 128
                + ((uint32_t)((k & 63) * 2) ^ (uint32_t)((n & 7) << 4));
    *(uint4*)(dst + base) = uo.u;
}

// ---------------------------------------------------------------------------
// Persistent fp16 warp-MMA GEMM: BM=128, BN=256, BK=128/stage, 2-stage ring,
// producer warp 8 + 8 compute warps, 288 threads, grid=148.
// Each CTA owns a CONTIGUOUS row-major tile range: bm fixed across nx
// consecutive tiles (A slab stays L2-hot), ring runs continuously so tile
// epilogues overlap the next tile's loads; prologue paid once per kernel.
// ---------------------------------------------------------------------------
#define NSTAGE      2
#define STAGE_BYTES 98304
#define GEMM_SMEM   (NSTAGE * STAGE_BYTES + 1024)
#define GTHREADS    288

template<int EPI>
__global__ __launch_bounds__(GTHREADS, 1) void gemm_f16_ker(
    const uint8_t* __restrict__ A, const uint8_t* __restrict__ B,
    const float* __restrict__ bias, const float* __restrict__ res,
    float* __restrict__ C, __half* __restrict__ Ch, uint8_t* __restrict__ Sx,
    int M, int N, int K, int ntiles, int nx)
{
    extern __shared__ uint8_t dynsmem[];
    __shared__ __align__(8) uint64_t s_bar[2 * NSTAGE];

    const int t = threadIdx.x, lane = t & 31, wid = t >> 5;

    // contiguous tile range for this CTA
    const int q = ntiles / NSM, r = ntiles % NSM;
    const int tstart = blockIdx.x * q + min(blockIdx.x, r);
    const int tend   = tstart + q + (blockIdx.x < r ? 1 : 0);

    const uint32_t sbase = (cvta_s(dynsmem) + 1023u) & ~1023u;
    uint32_t bfull[NSTAGE], bempty[NSTAGE];
    #pragma unroll
    for (int s = 0; s < NSTAGE; s++) {
        bfull[s]  = cvta_s(&s_bar[s]);
        bempty[s] = cvta_s(&s_bar[NSTAGE + s]);
    }
    if (t == 0) {
        #pragma unroll
        for (int s = 0; s < NSTAGE; s++) {
            mbar_init(bfull[s], 1);
            mbar_init(bempty[s], 8);
        }
    }
    __syncthreads();

    const int nc = K >> 7;    // 128-wide chunks per tile

    // ---- producer warp: streams chunks continuously across the tile range --
    if (wid == 8) {
        if (lane == 0) {
            int eph[NSTAGE];
            #pragma unroll
            for (int s = 0; s < NSTAGE; s++) eph[s] = 0;
            int gc = 0;
            for (int tile = tstart; tile < tend; tile++) {
                const int bm = (tile / nx) * 128;
                const int bn = (tile % nx) * 256;
                for (int c = 0; c < nc; c++, gc++) {
                    const int s = gc & (NSTAGE - 1);
                    if (gc >= NSTAGE) { mbar_wait(bempty[s], eph[s]); eph[s] ^= 1; }
                    const uint32_t sb = sbase + (uint32_t)s * STAGE_BYTES;
                    mbar_expect_tx(bfull[s], STAGE_BYTES);
                    const size_t c0 = (size_t)(2 * c), c1 = (size_t)(2 * c + 1);
                    bulk_ldg(sb,         A + (c0 * MPAD + bm) * 128, 16384, bfull[s]);
                    bulk_ldg(sb + 16384, A + (c1 * MPAD + bm) * 128, 16384, bfull[s]);
                    bulk_ldg(sb + 32768, B + (c0 * N + bn) * 128,    32768, bfull[s]);
                    bulk_ldg(sb + 65536, B + (c1 * N + bn) * 128,    32768, bfull[s]);
                }
            }
        }
        return;
    }

    // ---- compute warps (0..7) ----
    const int wm = wid >> 1, wn = wid & 1;
    const uint32_t sw = (uint32_t)(lane & 7) << 4;
    uint32_t rta[2], rtb[8];
    {
        const int rowoff = ((lane >> 3) & 1) * 8 + (lane & 7);
        rta[0] = (uint32_t)(wm * 32 +  0 + rowoff) * 128;
        rta[1] = (uint32_t)(wm * 32 + 16 + rowoff) * 128;
        const int nt = lane >> 4;
        #pragma unroll
        for (int j = 0; j < 8; j++)
            rtb[j] = (uint32_t)(wn * 128 + (2 * j + nt) * 8 + (lane & 7)) * 128;
    }
    const uint32_t khA16 = (uint32_t)(lane >> 4) * 16;
    const uint32_t khB16 = (uint32_t)((lane >> 3) & 1) * 16;

    int fph[NSTAGE];
    #pragma unroll
    for (int s = 0; s < NSTAGE; s++) fph[s] = 0;
    int gc = 0;

    for (int tile = tstart; tile < tend; tile++) {
        const int bm = (tile / nx) * 128;
        const int bn = (tile % nx) * 256;

        float acc[2][16][4];
        #pragma unroll
        for (int mi = 0; mi < 2; mi++)
            #pragma unroll
            for (int ni = 0; ni < 16; ni++)
                #pragma unroll
                for (int rr = 0; rr < 4; rr++) acc[mi][ni][rr] = 0.f;

        for (int c = 0; c < nc; c++, gc++) {
            const int s = gc & (NSTAGE - 1);
            mbar_wait(bfull[s], fph[s]); fph[s] ^= 1;
            const uint32_t sb = sbase + (uint32_t)s * STAGE_BYTES;
            #pragma unroll
            for (int kc2 = 0; kc2 < 2; kc2++) {
                const uint32_t aB = sb + (uint32_t)kc2 * 16384;
                const uint32_t bB = sb + 32768 + (uint32_t)kc2 * 32768;
                #pragma unroll
                for (int ks = 0; ks < 4; ks++) {
                    const uint32_t offA = (uint32_t)(ks * 32 + khA16) ^ sw;
                    const uint32_t offB = (uint32_t)(ks * 32 + khB16) ^ sw;
                    uint32_t a[2][4], b[8][4];
                    ldsm4(a[0], aB + rta[0] + offA);
                    ldsm4(a[1], aB + rta[1] + offA);
                    #pragma unroll
                    for (int j = 0; j < 8; j++)
                        ldsm4(b[j], bB + rtb[j] + offB);
                    if (kc2 == 1 && ks == 3 && lane == 0) mbar_arrive(bempty[s]);
                    #pragma unroll
                    for (int j = 0; j < 8; j++) {
                        mma_f16(acc[0][2 * j],     a[0], &b[j][0]);
                        mma_f16(acc[0][2 * j + 1], a[0], &b[j][2]);
                        mma_f16(acc[1][2 * j],     a[1], &b[j][0]);
                        mma_f16(acc[1][2 * j + 1], a[1], &b[j][2]);
                    }
                }
            }
        }

        // epilogue (overlaps producer's loads of the next tile)
        const int row0 = bm + wm * 32 + (lane >> 2);
        const int col0 = bn + wn * 128 + (lane & 3) * 2;
        #pragma unroll
        for (int mi = 0; mi < 2; mi++) {
            #pragma unroll
            for (int ni = 0; ni < 16; ni++) {
                const int col = col0 + ni * 8;
                float bb0 = 0.f, bb1 = 0.f;
                if (EPI != EPI_HALF) { bb0 = bias[col]; bb1 = bias[col + 1]; }
                #pragma unroll
                for (int half = 0; half < 2; half++) {
                    const int row = row0 + mi * 16 + half * 8;
                    if (row < M) {
                        float v0 = acc[mi][ni][half * 2]     + bb0;
                        float v1 = acc[mi][ni][half * 2 + 1] + bb1;
                        if (EPI == EPI_HALF) {
                            __half2 h2 = __floats2half2_rn(acc[mi][ni][half * 2],
                                                           acc[mi][ni][half * 2 + 1]);
                            *(uint32_t*)(Ch + (size_t)row * N + col) = *(uint32_t*)&h2;
                        } else if (EPI == EPI_GELU_H) {
                            v0 = 0.5f * v0 * (1.0f + erff(v0 * 0.70710678118654752f));
                            v1 = 0.5f * v1 * (1.0f + erff(v1 * 0.70710678118654752f));
                            __half2 h2 = __floats2half2_rn(v0, v1);
                            size_t base = ((size_t)(col >> 6) * MPAD + row) * 128
                                        + ((uint32_t)(2 * (col & 63)) ^ (uint32_t)((row & 7) << 4));
                            *(uint32_t*)(Sx + base) = *(uint32_t*)&h2;
                        } else { // EPI_BIAS_RES
                            const float2 r2 = *(const float2*)(res + (size_t)row * N + col);
                            *(float2*)(C + (size_t)row * N + col) =
                                make_float2(v0 + r2.x, v1 + r2.y);
                        }
                    }
                }
            }
        }
    }
}

// ---------------------------------------------------------------------------
// fp16 flash attention (R9/R11-verified): Q tile 64 (128 thr), KV tile 128
// double-buffered, exp2 softmax. smem 72K dynamic.
// ---------------------------------------------------------------------------
#define NITER2 ((SEQ + 127) / 128)   // 5
#define ATTN_SMEM (8192 + 4 * 16384)

__global__ __launch_bounds__(128) void attn_ker(const __half* __restrict__ qkv,
                                                uint8_t* __restrict__ oa)
{
    extern __shared__ uint8_t sm[];
    const uint32_t qsa = cvta_s(sm);
    const uint32_t ksa[2] = { qsa + 8192,  qsa + 8192 + 16384 };
    const uint32_t vsa[2] = { qsa + 40960, qsa + 40960 + 16384 };

    const int bh = blockIdx.y;
    const int b  = bh / NHEAD;
    const int h  = bh % NHEAD;
    const int q0 = blockIdx.x * 64;
    const int t  = threadIdx.x, lane = t & 31, w = t >> 5;

    auto issue_kv = [&](int j0, int bi) {
        for (int idx = t; idx < 1024; idx += 128) {
            const int r = idx >> 3, g = idx & 7;
            const int kr = j0 + r;
            const int krc = kr < SEQ ? kr : SEQ - 1;
            const uint32_t sz = kr < SEQ ? 16u : 0u;
            const __half* src = qkv + (size_t)(b * SEQ + krc) * C_QKV + h * HDIM + g * 8;
            const uint32_t off = r * 128 + ((g * 16) ^ ((r & 7) << 4));
            cp16(ksa[bi] + off, src + C_EMB,     sz);
            cp16(vsa[bi] + off, src + 2 * C_EMB, sz);
        }
        cp_commit();
    };

    issue_kv(0, 0);

    // load Q, pre-scaled by 0.125 * log2(e) -> S in log2 units
    const __half2 qsc = __floats2half2_rn(0.18033688f, 0.18033688f);
    for (int idx = t; idx < 1024; idx += 128) {
        const int r = idx >> 4, g = idx & 15;
        const int qr = q0 + r;
        uint2 val = make_uint2(0u, 0u);
        if (qr < SEQ) {
            val = *(const uint2*)(qkv + (size_t)(b * SEQ + qr) * C_QKV + h * HDIM + g * 4);
            __half2* hp = (__half2*)&val;
            hp[0] = __hmul2(hp[0], qsc);
            hp[1] = __hmul2(hp[1], qsc);
        }
        *(uint2*)(sm + r * 128 + ((g * 8) ^ ((r & 7) << 4))) = val;
    }
    __syncthreads();

    const uint32_t swl = (uint32_t)(lane & 7) << 4;
    const uint32_t nt  = (uint32_t)(lane >> 4);
    const uint32_t rhalf = (uint32_t)((lane >> 3) & 1);
    const uint32_t khA = nt * 16;
    const uint32_t khB = rhalf * 16;

    uint32_t qa[4][4];
    {
        const uint32_t rowA = (uint32_t)(w * 16 + rhalf * 8 + (lane & 7)) * 128;
        #pragma unroll
        for (int kc = 0; kc < 4; kc++)
            ldsm4(qa[kc], qsa + rowA + (((uint32_t)(kc * 32) + khA) ^ swl));
    }

    float m0 = -1e30f, m1 = -1e30f, l0 = 0.f, l1 = 0.f;
    float o[8][4];
    #pragma unroll
    for (int nj = 0; nj < 8; nj++)
        #pragma unroll
        for (int r = 0; r < 4; r++) o[nj][r] = 0.f;

    const int c0 = (lane & 3) * 2;

    for (int i = 0; i < NITER2; i++) {
        const int bi = i & 1;
        const int j0 = i * 128;
        cp_wait0();
        __syncthreads();
        if (i + 1 < NITER2) issue_kv(j0 + 128, bi ^ 1);

        // S = Q K^T (log2 units)
        float s[16][4];
        #pragma unroll
        for (int nj = 0; nj < 16; nj++)
            #pragma unroll
            for (int r = 0; r < 4; r++) s[nj][r] = 0.f;
        #pragma unroll
        for (int kc = 0; kc < 4; kc++) {
            #pragma unroll
            for (int j = 0; j < 8; j++) {
                uint32_t bb[4];
                const uint32_t row = (uint32_t)((2 * j + nt) * 8 + (lane & 7)) * 128;
                ldsm4(bb, ksa[bi] + row + (((uint32_t)(kc * 32) + khB) ^ swl));
                mma_f16(s[2 * j],     qa[kc], &bb[0]);
                mma_f16(s[2 * j + 1], qa[kc], &bb[2]);
            }
        }

        // mask only on the last tile (SEQ = 4*128 + 65)
        if (j0 + 128 > SEQ) {
            #pragma unroll
            for (int nj = 0; nj < 16; nj++) {
                const int col = j0 + nj * 8 + c0;
                if (col >= SEQ)     { s[nj][0] = -1e30f; s[nj][2] = -1e30f; }
                if (col + 1 >= SEQ) { s[nj][1] = -1e30f; s[nj][3] = -1e30f; }
            }
        }

        // online softmax (base-2)
        float mx0 = -1e30f, mx1 = -1e30f;
        #pragma unroll
        for (int nj = 0; nj < 16; nj++) {
            mx0 = fmaxf(mx0, fmaxf(s[nj][0], s[nj][1]));
            mx1 = fmaxf(mx1, fmaxf(s[nj][2], s[nj][3]));
        }
        mx0 = fmaxf(mx0, __shfl_xor_sync(0xFFFFFFFFu, mx0, 1));
        mx0 = fmaxf(mx0, __shfl_xor_sync(0xFFFFFFFFu, mx0, 2));
        mx1 = fmaxf(mx1, __shfl_xor_sync(0xFFFFFFFFu, mx1, 1));
        mx1 = fmaxf(mx1, __shfl_xor_sync(0xFFFFFFFFu, mx1, 2));
        const float nm0 = fmaxf(m0, mx0), nm1 = fmaxf(m1, mx1);
        const float cr0 = exp2f(m0 - nm0), cr1 = exp2f(m1 - nm1);
        m0 = nm0; m1 = nm1;
        float rs0 = 0.f, rs1 = 0.f;
        #pragma unroll
        for (int nj = 0; nj < 16; nj++) {
            float p0 = exp2f(s[nj][0] - m0);
            float p1 = exp2f(s[nj][1] - m0);
            float p2 = exp2f(s[nj][2] - m1);
            float p3 = exp2f(s[nj][3] - m1);
            s[nj][0] = p0; s[nj][1] = p1; s[nj][2] = p2; s[nj][3] = p3;
            rs0 += p0 + p1;
            rs1 += p2 + p3;
        }
        rs0 += __shfl_xor_sync(0xFFFFFFFFu, rs0, 1);
        rs0 += __shfl_xor_sync(0xFFFFFFFFu, rs0, 2);
        rs1 += __shfl_xor_sync(0xFFFFFFFFu, rs1, 1);
        rs1 += __shfl_xor_sync(0xFFFFFFFFu, rs1, 2);
        l0 = l0 * cr0 + rs0;
        l1 = l1 * cr1 + rs1;
        #pragma unroll
        for (int nj = 0; nj < 8; nj++) {
            o[nj][0] *= cr0; o[nj][1] *= cr0;
            o[nj][2] *= cr1; o[nj][3] *= cr1;
        }

        // O += P V
        #pragma unroll
        for (int kc = 0; kc < 8; kc++) {
            uint32_t pa[4];
            {
                __half2 t0 = __floats2half2_rn(s[2 * kc][0],     s[2 * kc][1]);
                __half2 t1 = __floats2half2_rn(s[2 * kc][2],     s[2 * kc][3]);
                __half2 t2 = __floats2half2_rn(s[2 * kc + 1][0], s[2 * kc + 1][1]);
                __half2 t3 = __floats2half2_rn(s[2 * kc + 1][2], s[2 * kc + 1][3]);
                pa[0] = *(uint32_t*)&t0; pa[1] = *(uint32_t*)&t1;
                pa[2] = *(uint32_t*)&t2; pa[3] = *(uint32_t*)&t3;
            }
            const uint32_t row = (uint32_t)(kc * 16 + rhalf * 8 + (lane & 7)) * 128;
            #pragma unroll
            for (int j = 0; j < 4; j++) {
                uint32_t vb[4];
                const uint32_t colb = 16u * (uint32_t)(2 * j + nt);
                ldsm4t(vb, vsa[bi] + row + (colb ^ swl));
                mma_f16(o[2 * j],     pa, &vb[0]);
                mma_f16(o[2 * j + 1], pa, &vb[2]);
            }
        }
    }

    // epilogue
    #pragma unroll
    for (int half = 0; half < 2; half++) {
        const int qr = q0 + w * 16 + (lane >> 2) + half * 8;
        if (qr < SEQ) {
            const float inv = 1.0f / (half ? l1 : l0);
            const size_t mtok = (size_t)b * SEQ + qr;
            const uint32_t swr = ((uint32_t)(mtok & 7)) << 4;
            const size_t rowbase = ((size_t)h * MPAD + mtok) * 128;
            #pragma unroll
            for (int nj = 0; nj < 8; nj++) {
                const int d = nj * 8 + c0;
                __half2 h2 = __floats2half2_rn(o[nj][half * 2] * inv,
                                               o[nj][half * 2 + 1] * inv);
                *(uint32_t*)(oa + rowbase + (((uint32_t)(2 * d)) ^ swr)) = *(uint32_t*)&h2;
            }
        }
    }
}

// ---------------------------------------------------------------------------
// Launch
// ---------------------------------------------------------------------------
extern "C" void kernel_launch(void* const* d_in, const int* in_sizes, int n_in,
                              void* d_out, int out_size)
{
    const float* x      = (const float*)d_in[0];
    const float* ln1_g  = (const float*)d_in[1];
    const float* ln1_b  = (const float*)d_in[2];
    const float* w_qkv  = (const float*)d_in[3];
    const float* w_proj = (const float*)d_in[4];
    const float* b_proj = (const float*)d_in[5];
    const float* ln2_g  = (const float*)d_in[6];
    const float* ln2_b  = (const float*)d_in[7];
    const float* w_fc1  = (const float*)d_in[8];
    const float* b_fc1  = (const float*)d_in[9];
    const float* w_fc2  = (const float*)d_in[10];
    const float* b_fc2  = (const float*)d_in[11];
    float* out = (float*)d_out;

    __half *p_qkvh, *p_w; float* p_x1;
    uint8_t *p_actA, *p_actB;
    cudaGetSymbolAddress((void**)&p_qkvh, g_qkvh);
    cudaGetSymbolAddress((void**)&p_x1,   g_x1);
    cudaGetSymbolAddress((void**)&p_actA, g_actA);
    cudaGetSymbolAddress((void**)&p_actB, g_actB);
    cudaGetSymbolAddress((void**)&p_w,    g_w);
    uint8_t* p_wb = (uint8_t*)p_w;

    cudaFuncSetAttribute(gemm_f16_ker<EPI_BIAS_RES>,
                         cudaFuncAttributeMaxDynamicSharedMemorySize, GEMM_SMEM);
    cudaFuncSetAttribute(gemm_f16_ker<EPI_GELU_H>,
                         cudaFuncAttributeMaxDynamicSharedMemorySize, GEMM_SMEM);
    cudaFuncSetAttribute(gemm_f16_ker<EPI_HALF>,
                         cudaFuncAttributeMaxDynamicSharedMemorySize, GEMM_SMEM);
    cudaFuncSetAttribute(attn_ker,
                         cudaFuncAttributeMaxDynamicSharedMemorySize, ATTN_SMEM);

    const int M = MTOK;
    const int MY = (M + 127) / 128;   // 289
    const dim3 blkT(32, 4);

    // 1) LN1 -> fp16 acts A
    ln_f16_ker<<<MTOK / 8, 256>>>(x, ln1_g, ln1_b, p_actA);
    // 2) convert w_qkv
    convT_ker<<<dim3(C_QKV / 32, C_EMB / 32), blkT>>>(w_qkv, p_wb, C_EMB, C_QKV);
    // 3) qkv = h @ w_qkv -> fp16 row-major
    gemm_f16_ker<EPI_HALF><<<NSM, GTHREADS, GEMM_SMEM>>>(
        p_actA, p_wb, nullptr, nullptr, nullptr, p_qkvh, nullptr,
        M, C_QKV, C_EMB, MY * (C_QKV / 256), C_QKV / 256);
    // 4) flash attention -> fp16 acts A
    attn_ker<<<dim3((SEQ + 63) / 64, BATCH * NHEAD), 128, ATTN_SMEM>>>(p_qkvh, p_actA);
    // 5) convert w_proj
    convT_ker<<<dim3(C_EMB / 32, C_EMB / 32), blkT>>>(w_proj, p_wb, C_EMB, C_EMB);
    // 6) x1 = x + att @ w_proj + b_proj
    gemm_f16_ker<EPI_BIAS_RES><<<NSM, GTHREADS, GEMM_SMEM>>>(
        p_actA, p_wb, b_proj, x, p_x1, nullptr, nullptr,
        M, C_EMB, C_EMB, MY * (C_EMB / 256), C_EMB / 256);
    // 7) LN2 -> fp16 acts A
    ln_f16_ker<<<MTOK / 8, 256>>>(p_x1, ln2_g, ln2_b, p_actA);
    // 8) convert w_fc1
    convT_ker<<<dim3(C_HID / 32, C_EMB / 32), blkT>>>(w_fc1, p_wb, C_EMB, C_HID);
    // 9) ff = gelu(h @ w_fc1 + b_fc1) -> fp16 acts B
    gemm_f16_ker<EPI_GELU_H><<<NSM, GTHREADS, GEMM_SMEM>>>(
        p_actA, p_wb, b_fc1, nullptr, nullptr, nullptr, p_actB,
        M, C_HID, C_EMB, MY * (C_HID / 256), C_HID / 256);
    // 10) convert w_fc2
    convT_ker<<<dim3(C_EMB / 32, C_HID / 32), blkT>>>(w_fc2, p_wb, C_HID, C_EMB);
    // 11) out = x1 + ff @ w_fc2 + b_fc2
    gemm_f16_ker<EPI_BIAS_RES><<<NSM, GTHREADS, GEMM_SMEM>>>(
        p_actB, p_wb, b_fc2, p_x1, out, nullptr, nullptr,
        M, C_EMB, C_HID, MY * (C_EMB / 256), C_EMB / 256);
}

// round 16
// speedup vs baseline: 1.0090x; 1.0090x over previous
#include <cuda_runtime.h>
#include <cuda_fp16.h>
#include <math.h>
#include <stdint.h>

// ---------------------------------------------------------------------------
// Problem constants
// ---------------------------------------------------------------------------
#define BATCH   64
#define SEQ     577
#define MTOK    (BATCH * SEQ)      // 36928
#define MPAD    36992              // 289 * 128
#define C_EMB   768
#define C_QKV   2304
#define C_HID   3072
#define NHEAD   12
#define HDIM    64

#define EPI_BIAS_RES  1
#define EPI_GELU_H    2
#define EPI_HALF      3

// ---------------------------------------------------------------------------
// Scratch (device globals)
// ---------------------------------------------------------------------------
__device__ __half g_qkvh[(size_t)MTOK * C_QKV];       // qkv proj, fp16 row-major
__device__ float  g_x1 [(size_t)MTOK * C_EMB];        // residual 1
// fp16 activations, chunked+swizzled: [K/64][MPAD rows][64 fp16 = 128B]
__device__ __half g_actA[(size_t)MPAD * C_EMB];
__device__ __half g_actB[(size_t)MPAD * C_HID];
// fp16 weights, transposed chunked+swizzled: [K/64][N][64 fp16] — one buffer each
__device__ __half g_wqkv [(size_t)C_EMB * C_QKV];
__device__ __half g_wproj[(size_t)C_EMB * C_EMB];
__device__ __half g_wfc1 [(size_t)C_EMB * C_HID];
__device__ __half g_wfc2 [(size_t)C_HID * C_EMB];

// ---------------------------------------------------------------------------
// PTX helpers
// ---------------------------------------------------------------------------
__device__ __forceinline__ uint32_t cvta_s(const void* p) {
    uint32_t a;
    asm("{ .reg .u64 t; cvta.to.shared.u64 t, %1; cvt.u32.u64 %0, t; }"
        : "=r"(a) : "l"(p));
    return a;
}
__device__ __forceinline__ void mbar_init(uint32_t mbar, uint32_t cnt) {
    asm volatile("mbarrier.init.shared.b64 [%0], %1;" :: "r"(mbar), "r"(cnt) : "memory");
}
__device__ __forceinline__ void mbar_expect_tx(uint32_t mbar, uint32_t bytes) {
    asm volatile("mbarrier.arrive.expect_tx.shared.b64 _, [%0], %1;"
                 :: "r"(mbar), "r"(bytes) : "memory");
}
__device__ __forceinline__ void mbar_arrive(uint32_t mbar) {
    asm volatile("mbarrier.arrive.shared.b64 _, [%0];" :: "r"(mbar) : "memory");
}
__device__ __forceinline__ void mbar_wait(uint32_t mbar, uint32_t phase) {
    asm volatile(
        "{\n\t"
        ".reg .pred P1;\n\t"
        "WAIT_LOOP_%=:\n\t"
        "mbarrier.try_wait.parity.acquire.cta.shared::cta.b64 P1, [%0], %1, 0x989680;\n\t"
        "@P1 bra.uni WAIT_DONE_%=;\n\t"
        "bra.uni WAIT_LOOP_%=;\n\t"
        "WAIT_DONE_%=:\n\t"
        "}"
        :: "r"(mbar), "r"(phase) : "memory");
}
__device__ __forceinline__ void bulk_ldg(uint32_t dst, const void* src,
                                         uint32_t bytes, uint32_t mbar) {
    asm volatile(
        "cp.async.bulk.shared::cluster.global.mbarrier::complete_tx::bytes "
        "[%0], [%1], %2, [%3];"
        :: "r"(dst), "l"(src), "r"(bytes), "r"(mbar) : "memory");
}
__device__ __forceinline__ void cp16(uint32_t dst, const void* src, uint32_t srcsize) {
    asm volatile("cp.async.cg.shared.global [%0], [%1], 16, %2;"
                 :: "r"(dst), "l"(src), "r"(srcsize) : "memory");
}
__device__ __forceinline__ void cp_commit() {
    asm volatile("cp.async.commit_group;" ::: "memory");
}
__device__ __forceinline__ void cp_wait0() {
    asm volatile("cp.async.wait_group 0;" ::: "memory");
}
__device__ __forceinline__ void ldsm4(uint32_t* r, uint32_t addr) {
    asm volatile("ldmatrix.sync.aligned.m8n8.x4.shared.b16 {%0,%1,%2,%3}, [%4];"
                 : "=r"(r[0]), "=r"(r[1]), "=r"(r[2]), "=r"(r[3]) : "r"(addr));
}
__device__ __forceinline__ void ldsm4t(uint32_t* r, uint32_t addr) {
    asm volatile("ldmatrix.sync.aligned.m8n8.x4.trans.shared.b16 {%0,%1,%2,%3}, [%4];"
                 : "=r"(r[0]), "=r"(r[1]), "=r"(r[2]), "=r"(r[3]) : "r"(addr));
}
__device__ __forceinline__ void mma_f16(float* c, const uint32_t* a, const uint32_t* b) {
    asm volatile(
        "mma.sync.aligned.m16n8k16.row.col.f32.f16.f16.f32 "
        "{%0,%1,%2,%3},{%4,%5,%6,%7},{%8,%9},{%0,%1,%2,%3};"
        : "+f"(c[0]), "+f"(c[1]), "+f"(c[2]), "+f"(c[3])
        : "r"(a[0]), "r"(a[1]), "r"(a[2]), "r"(a[3]), "r"(b[0]), "r"(b[1]));
}

// ---------------------------------------------------------------------------
// LN device function: warp-per-row, 8 rows per 256-thread block.
// ---------------------------------------------------------------------------
__device__ __forceinline__ void ln_row(const float* __restrict__ x,
                                       const float* __restrict__ gamma,
                                       const float* __restrict__ beta,
                                       uint8_t* __restrict__ dst,
                                       int row, int lane)
{
    const float* xr = x + (size_t)row * C_EMB;
    float v[24];
    float s = 0.f, s2 = 0.f;
    #pragma unroll
    for (int g = 0; g < 3; g++) {
        const float4* p = (const float4*)(xr + g * 256 + lane * 8);
        float4 a = p[0], b = p[1];
        v[g*8+0]=a.x; v[g*8+1]=a.y; v[g*8+2]=a.z; v[g*8+3]=a.w;
        v[g*8+4]=b.x; v[g*8+5]=b.y; v[g*8+6]=b.z; v[g*8+7]=b.w;
        #pragma unroll
        for (int i = 0; i < 8; i++) { s += v[g*8+i]; s2 += v[g*8+i]*v[g*8+i]; }
    }
    #pragma unroll
    for (int off = 16; off > 0; off >>= 1) {
        s  += __shfl_xor_sync(0xFFFFFFFFu, s,  off);
        s2 += __shfl_xor_sync(0xFFFFFFFFu, s2, off);
    }
    const float mean = s * (1.0f / C_EMB);
    const float rstd = rsqrtf(s2 * (1.0f / C_EMB) - mean * mean + 1e-5f);

    #pragma unroll
    for (int g = 0; g < 3; g++) {
        const int k = g * 256 + lane * 8;
        const float4* gp = (const float4*)(gamma + k);
        const float4* bp = (const float4*)(beta + k);
        float4 g0 = gp[0], g1 = gp[1], b0 = bp[0], b1 = bp[1];
        float gg[8] = {g0.x,g0.y,g0.z,g0.w,g1.x,g1.y,g1.z,g1.w};
        float bb[8] = {b0.x,b0.y,b0.z,b0.w,b1.x,b1.y,b1.z,b1.w};
        union { __half h[8]; uint4 u; } uo;
        #pragma unroll
        for (int i = 0; i < 8; i++)
            uo.h[i] = __float2half_rn((v[g*8+i] - mean) * rstd * gg[i] + bb[i]);
        size_t base = ((size_t)(k >> 6) * MPAD + row) * 128
                    + ((uint32_t)((k & 63) * 2) ^ (uint32_t)((row & 7) << 4));
        *(uint4*)(dst + base) = uo.u;
    }
}

// ---------------------------------------------------------------------------
// conv tile device function: 32-k x 64-n transpose+convert, 256 thr (64,4).
// ---------------------------------------------------------------------------
__device__ __forceinline__ void conv_tile(const float* __restrict__ w,
                                          uint8_t* __restrict__ dst,
                                          int N, int k0, int n0, int t)
{
    __shared__ float tile[32][65];
    const int tx = t & 63, ty = t >> 6;   // (64, 4)
    for (int i = ty; i < 32; i += 4)
        tile[i][tx] = w[(size_t)(k0 + i) * N + n0 + tx];
    __syncthreads();
    const int n = n0 + tx;
    const int k = k0 + ty * 8;
    union { __half h[8]; uint4 u; } uo;
    #pragma unroll
    for (int i = 0; i < 8; i++)
        uo.h[i] = __float2half_rn(tile[ty * 8 + i][tx]);
    size_t base = ((size_t)(k >> 6) * N + n) * 128
                + ((uint32_t)((k & 63) * 2) ^ (uint32_t)((n & 7) << 4));
    *(uint4*)(dst + base) = uo.u;
}

// ---------------------------------------------------------------------------
// prep kernel: LN1 (4616 blocks) + ALL 4 weight conversions (3456 blocks)
// fused into one launch so conversions overlap LN across SMs.
// ---------------------------------------------------------------------------
#define LN_BLKS   (MTOK / 8)                // 4616
#define QKV_BLKS  ((C_QKV/64)*(C_EMB/32))   // 864
#define PROJ_BLKS ((C_EMB/64)*(C_EMB/32))   // 288
#define FC1_BLKS  ((C_HID/64)*(C_EMB/32))   // 1152
#define FC2_BLKS  ((C_EMB/64)*(C_HID/32))   // 1152
#define PREP_BLKS (LN_BLKS + QKV_BLKS + PROJ_BLKS + FC1_BLKS + FC2_BLKS)

__global__ __launch_bounds__(256) void prep_ker(
    const float* __restrict__ x,
    const float* __restrict__ ln1_g, const float* __restrict__ ln1_b,
    const float* __restrict__ w_qkv, const float* __restrict__ w_proj,
    const float* __restrict__ w_fc1, const float* __restrict__ w_fc2,
    uint8_t* __restrict__ actA,
    uint8_t* __restrict__ dqkv, uint8_t* __restrict__ dproj,
    uint8_t* __restrict__ dfc1, uint8_t* __restrict__ dfc2)
{
    const int bid = blockIdx.x, t = threadIdx.x;
    if (bid < LN_BLKS) {
        ln_row(x, ln1_g, ln1_b, actA, bid * 8 + (t >> 5), t & 31);
        return;
    }
    int idx = bid - LN_BLKS;
    if (idx < QKV_BLKS) {
        conv_tile(w_qkv, dqkv, C_QKV, (idx / (C_QKV/64)) * 32, (idx % (C_QKV/64)) * 64, t);
        return;
    }
    idx -= QKV_BLKS;
    if (idx < PROJ_BLKS) {
        conv_tile(w_proj, dproj, C_EMB, (idx / (C_EMB/64)) * 32, (idx % (C_EMB/64)) * 64, t);
        return;
    }
    idx -= PROJ_BLKS;
    if (idx < FC1_BLKS) {
        conv_tile(w_fc1, dfc1, C_HID, (idx / (C_HID/64)) * 32, (idx % (C_HID/64)) * 64, t);
        return;
    }
    idx -= FC1_BLKS;
    conv_tile(w_fc2, dfc2, C_EMB, (idx / (C_EMB/64)) * 32, (idx % (C_EMB/64)) * 64, t);
}

// ---------------------------------------------------------------------------
// LN2 standalone (depends on proj output)
// ---------------------------------------------------------------------------
__global__ __launch_bounds__(256) void ln_f16_ker(const float* __restrict__ x,
                                                  const float* __restrict__ gamma,
                                                  const float* __restrict__ beta,
                                                  uint8_t* __restrict__ dst)
{
    ln_row(x, gamma, beta, dst, blockIdx.x * 8 + (threadIdx.x >> 5), threadIdx.x & 31);
}

// ---------------------------------------------------------------------------
// fp16 warp-MMA GEMM (R12-verified best): BM=128, BN=256, BK=128/stage,
// 2-stage ring, producer warp 8 + 8 compute warps, 288 threads.
// ---------------------------------------------------------------------------
#define NSTAGE      2
#define STAGE_BYTES 98304
#define GEMM_SMEM   (NSTAGE * STAGE_BYTES + 1024)
#define GTHREADS    288

template<int EPI>
__global__ __launch_bounds__(GTHREADS, 1) void gemm_f16_ker(
    const uint8_t* __restrict__ A, const uint8_t* __restrict__ B,
    const float* __restrict__ bias, const float* __restrict__ res,
    float* __restrict__ C, __half* __restrict__ Ch, uint8_t* __restrict__ Sx,
    int M, int N, int K)
{
    extern __shared__ uint8_t dynsmem[];
    __shared__ __align__(8) uint64_t s_bar[2 * NSTAGE];

    const int t = threadIdx.x, lane = t & 31, wid = t >> 5;
    const int bm = blockIdx.y * 128, bn = blockIdx.x * 256;

    const uint32_t sbase = (cvta_s(dynsmem) + 1023u) & ~1023u;
    uint32_t bfull[NSTAGE], bempty[NSTAGE];
    #pragma unroll
    for (int s = 0; s < NSTAGE; s++) {
        bfull[s]  = cvta_s(&s_bar[s]);
        bempty[s] = cvta_s(&s_bar[NSTAGE + s]);
    }
    if (t == 0) {
        #pragma unroll
        for (int s = 0; s < NSTAGE; s++) {
            mbar_init(bfull[s], 1);
            mbar_init(bempty[s], 8);
        }
    }
    __syncthreads();

    const int nc = K >> 7;

    // ---- producer warp ----
    if (wid == 8) {
        if (lane == 0) {
            int eph[NSTAGE];
            #pragma unroll
            for (int s = 0; s < NSTAGE; s++) eph[s] = 0;
            for (int c = 0; c < nc; c++) {
                const int s = c & (NSTAGE - 1);
                if (c >= NSTAGE) { mbar_wait(bempty[s], eph[s]); eph[s] ^= 1; }
                const uint32_t sb = sbase + (uint32_t)s * STAGE_BYTES;
                mbar_expect_tx(bfull[s], STAGE_BYTES);
                const size_t c0 = (size_t)(2 * c), c1 = (size_t)(2 * c + 1);
                bulk_ldg(sb,         A + (c0 * MPAD + bm) * 128, 16384, bfull[s]);
                bulk_ldg(sb + 16384, A + (c1 * MPAD + bm) * 128, 16384, bfull[s]);
                bulk_ldg(sb + 32768, B + (c0 * N + bn) * 128,    32768, bfull[s]);
                bulk_ldg(sb + 65536, B + (c1 * N + bn) * 128,    32768, bfull[s]);
            }
        }
        return;
    }

    // ---- compute warps (0..7) ----
    const int wm = wid >> 1, wn = wid & 1;
    const uint32_t sw = (uint32_t)(lane & 7) << 4;
    uint32_t rta[2], rtb[8];
    {
        const int rowoff = ((lane >> 3) & 1) * 8 + (lane & 7);
        rta[0] = (uint32_t)(wm * 32 +  0 + rowoff) * 128;
        rta[1] = (uint32_t)(wm * 32 + 16 + rowoff) * 128;
        const int nt = lane >> 4;
        #pragma unroll
        for (int j = 0; j < 8; j++)
            rtb[j] = (uint32_t)(wn * 128 + (2 * j + nt) * 8 + (lane & 7)) * 128;
    }
    const uint32_t khA16 = (uint32_t)(lane >> 4) * 16;
    const uint32_t khB16 = (uint32_t)((lane >> 3) & 1) * 16;

    float acc[2][16][4];
    #pragma unroll
    for (int mi = 0; mi < 2; mi++)
        #pragma unroll
        for (int ni = 0; ni < 16; ni++)
            #pragma unroll
            for (int r = 0; r < 4; r++) acc[mi][ni][r] = 0.f;

    int fph[NSTAGE];
    #pragma unroll
    for (int s = 0; s < NSTAGE; s++) fph[s] = 0;

    for (int c = 0; c < nc; c++) {
        const int s = c & (NSTAGE - 1);
        mbar_wait(bfull[s], fph[s]); fph[s] ^= 1;
        const uint32_t sb = sbase + (uint32_t)s * STAGE_BYTES;
        #pragma unroll
        for (int kc2 = 0; kc2 < 2; kc2++) {
            const uint32_t aB = sb + (uint32_t)kc2 * 16384;
            const uint32_t bB = sb + 32768 + (uint32_t)kc2 * 32768;
            #pragma unroll
            for (int ks = 0; ks < 4; ks++) {
                const uint32_t offA = (uint32_t)(ks * 32 + khA16) ^ sw;
                const uint32_t offB = (uint32_t)(ks * 32 + khB16) ^ sw;
                uint32_t a[2][4], b[8][4];
                ldsm4(a[0], aB + rta[0] + offA);
                ldsm4(a[1], aB + rta[1] + offA);
                #pragma unroll
                for (int j = 0; j < 8; j++)
                    ldsm4(b[j], bB + rtb[j] + offB);
                if (kc2 == 1 && ks == 3 && lane == 0) mbar_arrive(bempty[s]);
                #pragma unroll
                for (int j = 0; j < 8; j++) {
                    mma_f16(acc[0][2 * j],     a[0], &b[j][0]);
                    mma_f16(acc[0][2 * j + 1], a[0], &b[j][2]);
                    mma_f16(acc[1][2 * j],     a[1], &b[j][0]);
                    mma_f16(acc[1][2 * j + 1], a[1], &b[j][2]);
                }
            }
        }
    }

    // epilogue
    const int row0 = bm + wm * 32 + (lane >> 2);
    const int col0 = bn + wn * 128 + (lane & 3) * 2;
    #pragma unroll
    for (int mi = 0; mi < 2; mi++) {
        #pragma unroll
        for (int ni = 0; ni < 16; ni++) {
            const int col = col0 + ni * 8;
            float bb0 = 0.f, bb1 = 0.f;
            if (EPI != EPI_HALF) { bb0 = bias[col]; bb1 = bias[col + 1]; }
            #pragma unroll
            for (int half = 0; half < 2; half++) {
                const int row = row0 + mi * 16 + half * 8;
                if (row < M) {
                    float v0 = acc[mi][ni][half * 2]     + bb0;
                    float v1 = acc[mi][ni][half * 2 + 1] + bb1;
                    if (EPI == EPI_HALF) {
                        __half2 h2 = __floats2half2_rn(acc[mi][ni][half * 2],
                                                       acc[mi][ni][half * 2 + 1]);
                        *(uint32_t*)(Ch + (size_t)row * N + col) = *(uint32_t*)&h2;
                    } else if (EPI == EPI_GELU_H) {
                        v0 = 0.5f * v0 * (1.0f + erff(v0 * 0.70710678118654752f));
                        v1 = 0.5f * v1 * (1.0f + erff(v1 * 0.70710678118654752f));
                        __half2 h2 = __floats2half2_rn(v0, v1);
                        size_t base = ((size_t)(col >> 6) * MPAD + row) * 128
                                    + ((uint32_t)(2 * (col & 63)) ^ (uint32_t)((row & 7) << 4));
                        *(uint32_t*)(Sx + base) = *(uint32_t*)&h2;
                    } else { // EPI_BIAS_RES
                        const float2 r2 = *(const float2*)(res + (size_t)row * N + col);
                        *(float2*)(C + (size_t)row * N + col) =
                            make_float2(v0 + r2.x, v1 + r2.y);
                    }
                }
            }
        }
    }
}

// ---------------------------------------------------------------------------
// fp16 flash attention (R9/R11/R12-verified): Q tile 64 (128 thr), KV tile 128
// double-buffered, exp2 softmax. smem 72K dynamic.
// ---------------------------------------------------------------------------
#define NITER2 ((SEQ + 127) / 128)   // 5
#define ATTN_SMEM (8192 + 4 * 16384)

__global__ __launch_bounds__(128) void attn_ker(const __half* __restrict__ qkv,
                                                uint8_t* __restrict__ oa)
{
    extern __shared__ uint8_t sm[];
    const uint32_t qsa = cvta_s(sm);
    const uint32_t ksa[2] = { qsa + 8192,  qsa + 8192 + 16384 };
    const uint32_t vsa[2] = { qsa + 40960, qsa + 40960 + 16384 };

    const int bh = blockIdx.y;
    const int b  = bh / NHEAD;
    const int h  = bh % NHEAD;
    const int q0 = blockIdx.x * 64;
    const int t  = threadIdx.x, lane = t & 31, w = t >> 5;

    auto issue_kv = [&](int j0, int bi) {
        for (int idx = t; idx < 1024; idx += 128) {
            const int r = idx >> 3, g = idx & 7;
            const int kr = j0 + r;
            const int krc = kr < SEQ ? kr : SEQ - 1;
            const uint32_t sz = kr < SEQ ? 16u : 0u;
            const __half* src = qkv + (size_t)(b * SEQ + krc) * C_QKV + h * HDIM + g * 8;
            const uint32_t off = r * 128 + ((g * 16) ^ ((r & 7) << 4));
            cp16(ksa[bi] + off, src + C_EMB,     sz);
            cp16(vsa[bi] + off, src + 2 * C_EMB, sz);
        }
        cp_commit();
    };

    issue_kv(0, 0);

    const __half2 qsc = __floats2half2_rn(0.18033688f, 0.18033688f);
    for (int idx = t; idx < 1024; idx += 128) {
        const int r = idx >> 4, g = idx & 15;
        const int qr = q0 + r;
        uint2 val = make_uint2(0u, 0u);
        if (qr < SEQ) {
            val = *(const uint2*)(qkv + (size_t)(b * SEQ + qr) * C_QKV + h * HDIM + g * 4);
            __half2* hp = (__half2*)&val;
            hp[0] = __hmul2(hp[0], qsc);
            hp[1] = __hmul2(hp[1], qsc);
        }
        *(uint2*)(sm + r * 128 + ((g * 8) ^ ((r & 7) << 4))) = val;
    }
    __syncthreads();

    const uint32_t swl = (uint32_t)(lane & 7) << 4;
    const uint32_t nt  = (uint32_t)(lane >> 4);
    const uint32_t rhalf = (uint32_t)((lane >> 3) & 1);
    const uint32_t khA = nt * 16;
    const uint32_t khB = rhalf * 16;

    uint32_t qa[4][4];
    {
        const uint32_t rowA = (uint32_t)(w * 16 + rhalf * 8 + (lane & 7)) * 128;
        #pragma unroll
        for (int kc = 0; kc < 4; kc++)
            ldsm4(qa[kc], qsa + rowA + (((uint32_t)(kc * 32) + khA) ^ swl));
    }

    float m0 = -1e30f, m1 = -1e30f, l0 = 0.f, l1 = 0.f;
    float o[8][4];
    #pragma unroll
    for (int nj = 0; nj < 8; nj++)
        #pragma unroll
        for (int r = 0; r < 4; r++) o[nj][r] = 0.f;

    const int c0 = (lane & 3) * 2;

    for (int i = 0; i < NITER2; i++) {
        const int bi = i & 1;
        const int j0 = i * 128;
        cp_wait0();
        __syncthreads();
        if (i + 1 < NITER2) issue_kv(j0 + 128, bi ^ 1);

        float s[16][4];
        #pragma unroll
        for (int nj = 0; nj < 16; nj++)
            #pragma unroll
            for (int r = 0; r < 4; r++) s[nj][r] = 0.f;
        #pragma unroll
        for (int kc = 0; kc < 4; kc++) {
            #pragma unroll
            for (int j = 0; j < 8; j++) {
                uint32_t bb[4];
                const uint32_t row = (uint32_t)((2 * j + nt) * 8 + (lane & 7)) * 128;
                ldsm4(bb, ksa[bi] + row + (((uint32_t)(kc * 32) + khB) ^ swl));
                mma_f16(s[2 * j],     qa[kc], &bb[0]);
                mma_f16(s[2 * j + 1], qa[kc], &bb[2]);
            }
        }

        if (j0 + 128 > SEQ) {
            #pragma unroll
            for (int nj = 0; nj < 16; nj++) {
                const int col = j0 + nj * 8 + c0;
                if (col >= SEQ)     { s[nj][0] = -1e30f; s[nj][2] = -1e30f; }
                if (col + 1 >= SEQ) { s[nj][1] = -1e30f; s[nj][3] = -1e30f; }
            }
        }

        float mx0 = -1e30f, mx1 = -1e30f;
        #pragma unroll
        for (int nj = 0; nj < 16; nj++) {
            mx0 = fmaxf(mx0, fmaxf(s[nj][0], s[nj][1]));
            mx1 = fmaxf(mx1, fmaxf(s[nj][2], s[nj][3]));
        }
        mx0 = fmaxf(mx0, __shfl_xor_sync(0xFFFFFFFFu, mx0, 1));
        mx0 = fmaxf(mx0, __shfl_xor_sync(0xFFFFFFFFu, mx0, 2));
        mx1 = fmaxf(mx1, __shfl_xor_sync(0xFFFFFFFFu, mx1, 1));
        mx1 = fmaxf(mx1, __shfl_xor_sync(0xFFFFFFFFu, mx1, 2));
        const float nm0 = fmaxf(m0, mx0), nm1 = fmaxf(m1, mx1);
        const float cr0 = exp2f(m0 - nm0), cr1 = exp2f(m1 - nm1);
        m0 = nm0; m1 = nm1;
        float rs0 = 0.f, rs1 = 0.f;
        #pragma unroll
        for (int nj = 0; nj < 16; nj++) {
            float p0 = exp2f(s[nj][0] - m0);
            float p1 = exp2f(s[nj][1] - m0);
            float p2 = exp2f(s[nj][2] - m1);
            float p3 = exp2f(s[nj][3] - m1);
            s[nj][0] = p0; s[nj][1] = p1; s[nj][2] = p2; s[nj][3] = p3;
            rs0 += p0 + p1;
            rs1 += p2 + p3;
        }
        rs0 += __shfl_xor_sync(0xFFFFFFFFu, rs0, 1);
        rs0 += __shfl_xor_sync(0xFFFFFFFFu, rs0, 2);
        rs1 += __shfl_xor_sync(0xFFFFFFFFu, rs1, 1);
        rs1 += __shfl_xor_sync(0xFFFFFFFFu, rs1, 2);
        l0 = l0 * cr0 + rs0;
        l1 = l1 * cr1 + rs1;
        #pragma unroll
        for (int nj = 0; nj < 8; nj++) {
            o[nj][0] *= cr0; o[nj][1] *= cr0;
            o[nj][2] *= cr1; o[nj][3] *= cr1;
        }

        #pragma unroll
        for (int kc = 0; kc < 8; kc++) {
            uint32_t pa[4];
            {
                __half2 t0 = __floats2half2_rn(s[2 * kc][0],     s[2 * kc][1]);
                __half2 t1 = __floats2half2_rn(s[2 * kc][2],     s[2 * kc][3]);
                __half2 t2 = __floats2half2_rn(s[2 * kc + 1][0], s[2 * kc + 1][1]);
                __half2 t3 = __floats2half2_rn(s[2 * kc + 1][2], s[2 * kc + 1][3]);
                pa[0] = *(uint32_t*)&t0; pa[1] = *(uint32_t*)&t1;
                pa[2] = *(uint32_t*)&t2; pa[3] = *(uint32_t*)&t3;
            }
            const uint32_t row = (uint32_t)(kc * 16 + rhalf * 8 + (lane & 7)) * 128;
            #pragma unroll
            for (int j = 0; j < 4; j++) {
                uint32_t vb[4];
                const uint32_t colb = 16u * (uint32_t)(2 * j + nt);
                ldsm4t(vb, vsa[bi] + row + (colb ^ swl));
                mma_f16(o[2 * j],     pa, &vb[0]);
                mma_f16(o[2 * j + 1], pa, &vb[2]);
            }
        }
    }

    #pragma unroll
    for (int half = 0; half < 2; half++) {
        const int qr = q0 + w * 16 + (lane >> 2) + half * 8;
        if (qr < SEQ) {
            const float inv = 1.0f / (half ? l1 : l0);
            const size_t mtok = (size_t)b * SEQ + qr;
            const uint32_t swr = ((uint32_t)(mtok & 7)) << 4;
            const size_t rowbase = ((size_t)h * MPAD + mtok) * 128;
            #pragma unroll
            for (int nj = 0; nj < 8; nj++) {
                const int d = nj * 8 + c0;
                __half2 h2 = __floats2half2_rn(o[nj][half * 2] * inv,
                                               o[nj][half * 2 + 1] * inv);
                *(uint32_t*)(oa + rowbase + (((uint32_t)(2 * d)) ^ swr)) = *(uint32_t*)&h2;
            }
        }
    }
}

// ---------------------------------------------------------------------------
// Launch
// ---------------------------------------------------------------------------
extern "C" void kernel_launch(void* const* d_in, const int* in_sizes, int n_in,
                              void* d_out, int out_size)
{
    const float* x      = (const float*)d_in[0];
    const float* ln1_g  = (const float*)d_in[1];
    const float* ln1_b  = (const float*)d_in[2];
    const float* w_qkv  = (const float*)d_in[3];
    const float* w_proj = (const float*)d_in[4];
    const float* b_proj = (const float*)d_in[5];
    const float* ln2_g  = (const float*)d_in[6];
    const float* ln2_b  = (const float*)d_in[7];
    const float* w_fc1  = (const float*)d_in[8];
    const float* b_fc1  = (const float*)d_in[9];
    const float* w_fc2  = (const float*)d_in[10];
    const float* b_fc2  = (const float*)d_in[11];
    float* out = (float*)d_out;

    __half *p_qkvh; float* p_x1;
    uint8_t *p_actA, *p_actB, *p_wqkv, *p_wproj, *p_wfc1, *p_wfc2;
    cudaGetSymbolAddress((void**)&p_qkvh,  g_qkvh);
    cudaGetSymbolAddress((void**)&p_x1,    g_x1);
    cudaGetSymbolAddress((void**)&p_actA,  g_actA);
    cudaGetSymbolAddress((void**)&p_actB,  g_actB);
    cudaGetSymbolAddress((void**)&p_wqkv,  g_wqkv);
    cudaGetSymbolAddress((void**)&p_wproj, g_wproj);
    cudaGetSymbolAddress((void**)&p_wfc1,  g_wfc1);
    cudaGetSymbolAddress((void**)&p_wfc2,  g_wfc2);

    cudaFuncSetAttribute(gemm_f16_ker<EPI_BIAS_RES>,
                         cudaFuncAttributeMaxDynamicSharedMemorySize, GEMM_SMEM);
    cudaFuncSetAttribute(gemm_f16_ker<EPI_GELU_H>,
                         cudaFuncAttributeMaxDynamicSharedMemorySize, GEMM_SMEM);
    cudaFuncSetAttribute(gemm_f16_ker<EPI_HALF>,
                         cudaFuncAttributeMaxDynamicSharedMemorySize, GEMM_SMEM);
    cudaFuncSetAttribute(attn_ker,
                         cudaFuncAttributeMaxDynamicSharedMemorySize, ATTN_SMEM);

    const int M = MTOK;
    const int MY = (M + 127) / 128;   // 289

    // 1) prep: LN1 + ALL weight conversions (one launch)
    prep_ker<<<PREP_BLKS, 256>>>(x, ln1_g, ln1_b, w_qkv, w_proj, w_fc1, w_fc2,
                                 p_actA, p_wqkv, p_wproj, p_wfc1, p_wfc2);
    // 2) qkv = h @ w_qkv -> fp16 row-major
    gemm_f16_ker<EPI_HALF><<<dim3(C_QKV / 256, MY), GTHREADS, GEMM_SMEM>>>(
        p_actA, p_wqkv, nullptr, nullptr, nullptr, p_qkvh, nullptr, M, C_QKV, C_EMB);
    // 3) flash attention -> fp16 acts A
    attn_ker<<<dim3((SEQ + 63) / 64, BATCH * NHEAD), 128, ATTN_SMEM>>>(p_qkvh, p_actA);
    // 4) x1 = x + att @ w_proj + b_proj
    gemm_f16_ker<EPI_BIAS_RES><<<dim3(C_EMB / 256, MY), GTHREADS, GEMM_SMEM>>>(
        p_actA, p_wproj, b_proj, x, p_x1, nullptr, nullptr, M, C_EMB, C_EMB);
    // 5) LN2 -> fp16 acts A
    ln_f16_ker<<<MTOK / 8, 256>>>(p_x1, ln2_g, ln2_b, p_actA);
    // 6) ff = gelu(h @ w_fc1 + b_fc1) -> fp16 acts B
    gemm_f16_ker<EPI_GELU_H><<<dim3(C_HID / 256, MY), GTHREADS, GEMM_SMEM>>>(
        p_actA, p_wfc1, b_fc1, nullptr, nullptr, nullptr, p_actB, M, C_HID, C_EMB);
    // 7) out = x1 + ff @ w_fc2 + b_fc2
    gemm_f16_ker<EPI_BIAS_RES><<<dim3(C_EMB / 256, MY), GTHREADS, GEMM_SMEM>>>(
        p_actB, p_wfc2, b_fc2, p_x1, out, nullptr, nullptr, M, C_EMB, C_HID);
}

// round 17
// speedup vs baseline: 1.0381x; 1.0288x over previous
#include <cuda_runtime.h>
#include <cuda_fp16.h>
#include <math.h>
#include <stdint.h>

// ---------------------------------------------------------------------------
// Problem constants
// ---------------------------------------------------------------------------
#define BATCH   64
#define SEQ     577
#define MTOK    (BATCH * SEQ)      // 36928
#define MPAD    36992              // 289 * 128
#define C_EMB   768
#define C_QKV   2304
#define C_HID   3072
#define NHEAD   12
#define HDIM    64

#define EPI_BIAS_RES  1
#define EPI_GELU_H    2
#define EPI_HALF      3

// ---------------------------------------------------------------------------
// Scratch (device globals)
// ---------------------------------------------------------------------------
__device__ __half g_qkvh[(size_t)MTOK * C_QKV];       // qkv proj, fp16 row-major
__device__ float  g_x1 [(size_t)MTOK * C_EMB];        // residual 1
// fp16 activations, chunked+swizzled: [K/64][MPAD rows][64 fp16 = 128B]
__device__ __half g_actA[(size_t)MPAD * C_EMB];
__device__ __half g_actB[(size_t)MPAD * C_HID];
// fp16 weights, transposed chunked+swizzled: [K/64][N][64 fp16] — one buffer each
__device__ __half g_wqkv [(size_t)C_EMB * C_QKV];
__device__ __half g_wproj[(size_t)C_EMB * C_EMB];
__device__ __half g_wfc1 [(size_t)C_EMB * C_HID];
__device__ __half g_wfc2 [(size_t)C_HID * C_EMB];

// ---------------------------------------------------------------------------
// PTX helpers
// ---------------------------------------------------------------------------
__device__ __forceinline__ uint32_t cvta_s(const void* p) {
    uint32_t a;
    asm("{ .reg .u64 t; cvta.to.shared.u64 t, %1; cvt.u32.u64 %0, t; }"
        : "=r"(a) : "l"(p));
    return a;
}
__device__ __forceinline__ void mbar_init(uint32_t mbar, uint32_t cnt) {
    asm volatile("mbarrier.init.shared.b64 [%0], %1;" :: "r"(mbar), "r"(cnt) : "memory");
}
__device__ __forceinline__ void mbar_expect_tx(uint32_t mbar, uint32_t bytes) {
    asm volatile("mbarrier.arrive.expect_tx.shared.b64 _, [%0], %1;"
                 :: "r"(mbar), "r"(bytes) : "memory");
}
__device__ __forceinline__ void mbar_arrive(uint32_t mbar) {
    asm volatile("mbarrier.arrive.shared.b64 _, [%0];" :: "r"(mbar) : "memory");
}
__device__ __forceinline__ void mbar_wait(uint32_t mbar, uint32_t phase) {
    asm volatile(
        "{\n\t"
        ".reg .pred P1;\n\t"
        "WAIT_LOOP_%=:\n\t"
        "mbarrier.try_wait.parity.acquire.cta.shared::cta.b64 P1, [%0], %1, 0x989680;\n\t"
        "@P1 bra.uni WAIT_DONE_%=;\n\t"
        "bra.uni WAIT_LOOP_%=;\n\t"
        "WAIT_DONE_%=:\n\t"
        "}"
        :: "r"(mbar), "r"(phase) : "memory");
}
__device__ __forceinline__ void bulk_ldg(uint32_t dst, const void* src,
                                         uint32_t bytes, uint32_t mbar) {
    asm volatile(
        "cp.async.bulk.shared::cluster.global.mbarrier::complete_tx::bytes "
        "[%0], [%1], %2, [%3];"
        :: "r"(dst), "l"(src), "r"(bytes), "r"(mbar) : "memory");
}
__device__ __forceinline__ void cp16(uint32_t dst, const void* src, uint32_t srcsize) {
    asm volatile("cp.async.cg.shared.global [%0], [%1], 16, %2;"
                 :: "r"(dst), "l"(src), "r"(srcsize) : "memory");
}
__device__ __forceinline__ void cp_commit() {
    asm volatile("cp.async.commit_group;" ::: "memory");
}
__device__ __forceinline__ void cp_wait0() {
    asm volatile("cp.async.wait_group 0;" ::: "memory");
}
__device__ __forceinline__ void ldsm4(uint32_t* r, uint32_t addr) {
    asm volatile("ldmatrix.sync.aligned.m8n8.x4.shared.b16 {%0,%1,%2,%3}, [%4];"
                 : "=r"(r[0]), "=r"(r[1]), "=r"(r[2]), "=r"(r[3]) : "r"(addr));
}
__device__ __forceinline__ void ldsm4t(uint32_t* r, uint32_t addr) {
    asm volatile("ldmatrix.sync.aligned.m8n8.x4.trans.shared.b16 {%0,%1,%2,%3}, [%4];"
                 : "=r"(r[0]), "=r"(r[1]), "=r"(r[2]), "=r"(r[3]) : "r"(addr));
}
__device__ __forceinline__ void mma_f16(float* c, const uint32_t* a, const uint32_t* b) {
    asm volatile(
        "mma.sync.aligned.m16n8k16.row.col.f32.f16.f16.f32 "
        "{%0,%1,%2,%3},{%4,%5,%6,%7},{%8,%9},{%0,%1,%2,%3};"
        : "+f"(c[0]), "+f"(c[1]), "+f"(c[2]), "+f"(c[3])
        : "r"(a[0]), "r"(a[1]), "r"(a[2]), "r"(a[3]), "r"(b[0]), "r"(b[1]));
}

// ---------------------------------------------------------------------------
// LN device function: warp-per-row, 8 rows per 256-thread block.
// ---------------------------------------------------------------------------
__device__ __forceinline__ void ln_row(const float* __restrict__ x,
                                       const float* __restrict__ gamma,
                                       const float* __restrict__ beta,
                                       uint8_t* __restrict__ dst,
                                       int row, int lane)
{
    const float* xr = x + (size_t)row * C_EMB;
    float v[24];
    float s = 0.f, s2 = 0.f;
    #pragma unroll
    for (int g = 0; g < 3; g++) {
        const float4* p = (const float4*)(xr + g * 256 + lane * 8);
        float4 a = p[0], b = p[1];
        v[g*8+0]=a.x; v[g*8+1]=a.y; v[g*8+2]=a.z; v[g*8+3]=a.w;
        v[g*8+4]=b.x; v[g*8+5]=b.y; v[g*8+6]=b.z; v[g*8+7]=b.w;
        #pragma unroll
        for (int i = 0; i < 8; i++) { s += v[g*8+i]; s2 += v[g*8+i]*v[g*8+i]; }
    }
    #pragma unroll
    for (int off = 16; off > 0; off >>= 1) {
        s  += __shfl_xor_sync(0xFFFFFFFFu, s,  off);
        s2 += __shfl_xor_sync(0xFFFFFFFFu, s2, off);
    }
    const float mean = s * (1.0f / C_EMB);
    const float rstd = rsqrtf(s2 * (1.0f / C_EMB) - mean * mean + 1e-5f);

    #pragma unroll
    for (int g = 0; g < 3; g++) {
        const int k = g * 256 + lane * 8;
        const float4* gp = (const float4*)(gamma + k);
        const float4* bp = (const float4*)(beta + k);
        float4 g0 = gp[0], g1 = gp[1], b0 = bp[0], b1 = bp[1];
        float gg[8] = {g0.x,g0.y,g0.z,g0.w,g1.x,g1.y,g1.z,g1.w};
        float bb[8] = {b0.x,b0.y,b0.z,b0.w,b1.x,b1.y,b1.z,b1.w};
        union { __half h[8]; uint4 u; } uo;
        #pragma unroll
        for (int i = 0; i < 8; i++)
            uo.h[i] = __float2half_rn((v[g*8+i] - mean) * rstd * gg[i] + bb[i]);
        size_t base = ((size_t)(k >> 6) * MPAD + row) * 128
                    + ((uint32_t)((k & 63) * 2) ^ (uint32_t)((row & 7) << 4));
        *(uint4*)(dst + base) = uo.u;
    }
}

// ---------------------------------------------------------------------------
// conv tile device function: 32-k x 64-n transpose+convert, 256 thr (64,4).
// ---------------------------------------------------------------------------
__device__ __forceinline__ void conv_tile(const float* __restrict__ w,
                                          uint8_t* __restrict__ dst,
                                          int N, int k0, int n0, int t)
{
    __shared__ float tile[32][65];
    const int tx = t & 63, ty = t >> 6;   // (64, 4)
    for (int i = ty; i < 32; i += 4)
        tile[i][tx] = w[(size_t)(k0 + i) * N + n0 + tx];
    __syncthreads();
    const int n = n0 + tx;
    const int k = k0 + ty * 8;
    union { __half h[8]; uint4 u; } uo;
    #pragma unroll
    for (int i = 0; i < 8; i++)
        uo.h[i] = __float2half_rn(tile[ty * 8 + i][tx]);
    size_t base = ((size_t)(k >> 6) * N + n) * 128
                + ((uint32_t)((k & 63) * 2) ^ (uint32_t)((n & 7) << 4));
    *(uint4*)(dst + base) = uo.u;
}

// ---------------------------------------------------------------------------
// prep kernel: LN1 + ALL 4 weight conversions fused (R16-verified)
// ---------------------------------------------------------------------------
#define LN_BLKS   (MTOK / 8)                // 4616
#define QKV_BLKS  ((C_QKV/64)*(C_EMB/32))   // 864
#define PROJ_BLKS ((C_EMB/64)*(C_EMB/32))   // 288
#define FC1_BLKS  ((C_HID/64)*(C_EMB/32))   // 1152
#define FC2_BLKS  ((C_EMB/64)*(C_HID/32))   // 1152
#define PREP_BLKS (LN_BLKS + QKV_BLKS + PROJ_BLKS + FC1_BLKS + FC2_BLKS)

__global__ __launch_bounds__(256) void prep_ker(
    const float* __restrict__ x,
    const float* __restrict__ ln1_g, const float* __restrict__ ln1_b,
    const float* __restrict__ w_qkv, const float* __restrict__ w_proj,
    const float* __restrict__ w_fc1, const float* __restrict__ w_fc2,
    uint8_t* __restrict__ actA,
    uint8_t* __restrict__ dqkv, uint8_t* __restrict__ dproj,
    uint8_t* __restrict__ dfc1, uint8_t* __restrict__ dfc2)
{
    const int bid = blockIdx.x, t = threadIdx.x;
    if (bid < LN_BLKS) {
        ln_row(x, ln1_g, ln1_b, actA, bid * 8 + (t >> 5), t & 31);
        return;
    }
    int idx = bid - LN_BLKS;
    if (idx < QKV_BLKS) {
        conv_tile(w_qkv, dqkv, C_QKV, (idx / (C_QKV/64)) * 32, (idx % (C_QKV/64)) * 64, t);
        return;
    }
    idx -= QKV_BLKS;
    if (idx < PROJ_BLKS) {
        conv_tile(w_proj, dproj, C_EMB, (idx / (C_EMB/64)) * 32, (idx % (C_EMB/64)) * 64, t);
        return;
    }
    idx -= PROJ_BLKS;
    if (idx < FC1_BLKS) {
        conv_tile(w_fc1, dfc1, C_HID, (idx / (C_HID/64)) * 32, (idx % (C_HID/64)) * 64, t);
        return;
    }
    idx -= FC1_BLKS;
    conv_tile(w_fc2, dfc2, C_EMB, (idx / (C_EMB/64)) * 32, (idx % (C_EMB/64)) * 64, t);
}

// ---------------------------------------------------------------------------
// LN2 standalone (depends on proj output)
// ---------------------------------------------------------------------------
__global__ __launch_bounds__(256) void ln_f16_ker(const float* __restrict__ x,
                                                  const float* __restrict__ gamma,
                                                  const float* __restrict__ beta,
                                                  uint8_t* __restrict__ dst)
{
    ln_row(x, gamma, beta, dst, blockIdx.x * 8 + (threadIdx.x >> 5), threadIdx.x & 31);
}

// ---------------------------------------------------------------------------
// fp16 warp-MMA GEMM: BM=128, BN=256, BK=128/stage, 2-stage ring.
// NEW: 16 compute warps (4x4 grid, warp tile 32x64, 64 accums) + producer
// warp 16 = 544 threads -> 4 compute warps per SMSP (was 2) to fix the
// measured issue=17%/occ=13% bottleneck. Regs/thread ~115 (cap 120).
// ---------------------------------------------------------------------------
#define NSTAGE      2
#define STAGE_BYTES 98304
#define GEMM_SMEM   (NSTAGE * STAGE_BYTES + 1024)
#define GTHREADS    544

template<int EPI>
__global__ __launch_bounds__(GTHREADS, 1) void gemm_f16_ker(
    const uint8_t* __restrict__ A, const uint8_t* __restrict__ B,
    const float* __restrict__ bias, const float* __restrict__ res,
    float* __restrict__ C, __half* __restrict__ Ch, uint8_t* __restrict__ Sx,
    int M, int N, int K)
{
    extern __shared__ uint8_t dynsmem[];
    __shared__ __align__(8) uint64_t s_bar[2 * NSTAGE];

    const int t = threadIdx.x, lane = t & 31, wid = t >> 5;
    const int bm = blockIdx.y * 128, bn = blockIdx.x * 256;

    const uint32_t sbase = (cvta_s(dynsmem) + 1023u) & ~1023u;
    uint32_t bfull[NSTAGE], bempty[NSTAGE];
    #pragma unroll
    for (int s = 0; s < NSTAGE; s++) {
        bfull[s]  = cvta_s(&s_bar[s]);
        bempty[s] = cvta_s(&s_bar[NSTAGE + s]);
    }
    if (t == 0) {
        #pragma unroll
        for (int s = 0; s < NSTAGE; s++) {
            mbar_init(bfull[s], 1);
            mbar_init(bempty[s], 16);
        }
    }
    __syncthreads();

    const int nc = K >> 7;

    // ---- producer warp (wid 16) ----
    if (wid == 16) {
        if (lane == 0) {
            int eph[NSTAGE];
            #pragma unroll
            for (int s = 0; s < NSTAGE; s++) eph[s] = 0;
            for (int c = 0; c < nc; c++) {
                const int s = c & (NSTAGE - 1);
                if (c >= NSTAGE) { mbar_wait(bempty[s], eph[s]); eph[s] ^= 1; }
                const uint32_t sb = sbase + (uint32_t)s * STAGE_BYTES;
                mbar_expect_tx(bfull[s], STAGE_BYTES);
                const size_t c0 = (size_t)(2 * c), c1 = (size_t)(2 * c + 1);
                bulk_ldg(sb,         A + (c0 * MPAD + bm) * 128, 16384, bfull[s]);
                bulk_ldg(sb + 16384, A + (c1 * MPAD + bm) * 128, 16384, bfull[s]);
                bulk_ldg(sb + 32768, B + (c0 * N + bn) * 128,    32768, bfull[s]);
                bulk_ldg(sb + 65536, B + (c1 * N + bn) * 128,    32768, bfull[s]);
            }
        }
        return;
    }

    // ---- compute warps (0..15), 4x4 grid: warp tile 32 x 64 ----
    const int wm = wid >> 2, wn = wid & 3;
    const uint32_t sw = (uint32_t)(lane & 7) << 4;
    uint32_t rta[2], rtb[4];
    {
        const int rowoff = ((lane >> 3) & 1) * 8 + (lane & 7);
        rta[0] = (uint32_t)(wm * 32 +  0 + rowoff) * 128;
        rta[1] = (uint32_t)(wm * 32 + 16 + rowoff) * 128;
        const int nt = lane >> 4;
        #pragma unroll
        for (int j = 0; j < 4; j++)
            rtb[j] = (uint32_t)(wn * 64 + (2 * j + nt) * 8 + (lane & 7)) * 128;
    }
    const uint32_t khA16 = (uint32_t)(lane >> 4) * 16;
    const uint32_t khB16 = (uint32_t)((lane >> 3) & 1) * 16;

    float acc[2][8][4];
    #pragma unroll
    for (int mi = 0; mi < 2; mi++)
        #pragma unroll
        for (int ni = 0; ni < 8; ni++)
            #pragma unroll
            for (int r = 0; r < 4; r++) acc[mi][ni][r] = 0.f;

    int fph[NSTAGE];
    #pragma unroll
    for (int s = 0; s < NSTAGE; s++) fph[s] = 0;

    for (int c = 0; c < nc; c++) {
        const int s = c & (NSTAGE - 1);
        mbar_wait(bfull[s], fph[s]); fph[s] ^= 1;
        const uint32_t sb = sbase + (uint32_t)s * STAGE_BYTES;
        #pragma unroll
        for (int kc2 = 0; kc2 < 2; kc2++) {
            const uint32_t aB = sb + (uint32_t)kc2 * 16384;
            const uint32_t bB = sb + 32768 + (uint32_t)kc2 * 32768;
            #pragma unroll
            for (int ks = 0; ks < 4; ks++) {
                const uint32_t offA = (uint32_t)(ks * 32 + khA16) ^ sw;
                const uint32_t offB = (uint32_t)(ks * 32 + khB16) ^ sw;
                uint32_t a[2][4], b[4][4];
                ldsm4(a[0], aB + rta[0] + offA);
                ldsm4(a[1], aB + rta[1] + offA);
                #pragma unroll
                for (int j = 0; j < 4; j++)
                    ldsm4(b[j], bB + rtb[j] + offB);
                if (kc2 == 1 && ks == 3 && lane == 0) mbar_arrive(bempty[s]);
                #pragma unroll
                for (int j = 0; j < 4; j++) {
                    mma_f16(acc[0][2 * j],     a[0], &b[j][0]);
                    mma_f16(acc[0][2 * j + 1], a[0], &b[j][2]);
                    mma_f16(acc[1][2 * j],     a[1], &b[j][0]);
                    mma_f16(acc[1][2 * j + 1], a[1], &b[j][2]);
                }
            }
        }
    }

    // epilogue
    const int row0 = bm + wm * 32 + (lane >> 2);
    const int col0 = bn + wn * 64 + (lane & 3) * 2;
    #pragma unroll
    for (int mi = 0; mi < 2; mi++) {
        #pragma unroll
        for (int ni = 0; ni < 8; ni++) {
            const int col = col0 + ni * 8;
            float bb0 = 0.f, bb1 = 0.f;
            if (EPI != EPI_HALF) { bb0 = bias[col]; bb1 = bias[col + 1]; }
            #pragma unroll
            for (int half = 0; half < 2; half++) {
                const int row = row0 + mi * 16 + half * 8;
                if (row < M) {
                    float v0 = acc[mi][ni][half * 2]     + bb0;
                    float v1 = acc[mi][ni][half * 2 + 1] + bb1;
                    if (EPI == EPI_HALF) {
                        __half2 h2 = __floats2half2_rn(acc[mi][ni][half * 2],
                                                       acc[mi][ni][half * 2 + 1]);
                        *(uint32_t*)(Ch + (size_t)row * N + col) = *(uint32_t*)&h2;
                    } else if (EPI == EPI_GELU_H) {
                        v0 = 0.5f * v0 * (1.0f + erff(v0 * 0.70710678118654752f));
                        v1 = 0.5f * v1 * (1.0f + erff(v1 * 0.70710678118654752f));
                        __half2 h2 = __floats2half2_rn(v0, v1);
                        size_t base = ((size_t)(col >> 6) * MPAD + row) * 128
                                    + ((uint32_t)(2 * (col & 63)) ^ (uint32_t)((row & 7) << 4));
                        *(uint32_t*)(Sx + base) = *(uint32_t*)&h2;
                    } else { // EPI_BIAS_RES
                        const float2 r2 = *(const float2*)(res + (size_t)row * N + col);
                        *(float2*)(C + (size_t)row * N + col) =
                            make_float2(v0 + r2.x, v1 + r2.y);
                    }
                }
            }
        }
    }
}

// ---------------------------------------------------------------------------
// fp16 flash attention (frozen since R9): Q tile 64 (128 thr), KV tile 128
// double-buffered, exp2 softmax. smem 72K dynamic.
// ---------------------------------------------------------------------------
#define NITER2 ((SEQ + 127) / 128)   // 5
#define ATTN_SMEM (8192 + 4 * 16384)

__global__ __launch_bounds__(128) void attn_ker(const __half* __restrict__ qkv,
                                                uint8_t* __restrict__ oa)
{
    extern __shared__ uint8_t sm[];
    const uint32_t qsa = cvta_s(sm);
    const uint32_t ksa[2] = { qsa + 8192,  qsa + 8192 + 16384 };
    const uint32_t vsa[2] = { qsa + 40960, qsa + 40960 + 16384 };

    const int bh = blockIdx.y;
    const int b  = bh / NHEAD;
    const int h  = bh % NHEAD;
    const int q0 = blockIdx.x * 64;
    const int t  = threadIdx.x, lane = t & 31, w = t >> 5;

    auto issue_kv = [&](int j0, int bi) {
        for (int idx = t; idx < 1024; idx += 128) {
            const int r = idx >> 3, g = idx & 7;
            const int kr = j0 + r;
            const int krc = kr < SEQ ? kr : SEQ - 1;
            const uint32_t sz = kr < SEQ ? 16u : 0u;
            const __half* src = qkv + (size_t)(b * SEQ + krc) * C_QKV + h * HDIM + g * 8;
            const uint32_t off = r * 128 + ((g * 16) ^ ((r & 7) << 4));
            cp16(ksa[bi] + off, src + C_EMB,     sz);
            cp16(vsa[bi] + off, src + 2 * C_EMB, sz);
        }
        cp_commit();
    };

    issue_kv(0, 0);

    const __half2 qsc = __floats2half2_rn(0.18033688f, 0.18033688f);
    for (int idx = t; idx < 1024; idx += 128) {
        const int r = idx >> 4, g = idx & 15;
        const int qr = q0 + r;
        uint2 val = make_uint2(0u, 0u);
        if (qr < SEQ) {
            val = *(const uint2*)(qkv + (size_t)(b * SEQ + qr) * C_QKV + h * HDIM + g * 4);
            __half2* hp = (__half2*)&val;
            hp[0] = __hmul2(hp[0], qsc);
            hp[1] = __hmul2(hp[1], qsc);
        }
        *(uint2*)(sm + r * 128 + ((g * 8) ^ ((r & 7) << 4))) = val;
    }
    __syncthreads();

    const uint32_t swl = (uint32_t)(lane & 7) << 4;
    const uint32_t nt  = (uint32_t)(lane >> 4);
    const uint32_t rhalf = (uint32_t)((lane >> 3) & 1);
    const uint32_t khA = nt * 16;
    const uint32_t khB = rhalf * 16;

    uint32_t qa[4][4];
    {
        const uint32_t rowA = (uint32_t)(w * 16 + rhalf * 8 + (lane & 7)) * 128;
        #pragma unroll
        for (int kc = 0; kc < 4; kc++)
            ldsm4(qa[kc], qsa + rowA + (((uint32_t)(kc * 32) + khA) ^ swl));
    }

    float m0 = -1e30f, m1 = -1e30f, l0 = 0.f, l1 = 0.f;
    float o[8][4];
    #pragma unroll
    for (int nj = 0; nj < 8; nj++)
        #pragma unroll
        for (int r = 0; r < 4; r++) o[nj][r] = 0.f;

    const int c0 = (lane & 3) * 2;

    for (int i = 0; i < NITER2; i++) {
        const int bi = i & 1;
        const int j0 = i * 128;
        cp_wait0();
        __syncthreads();
        if (i + 1 < NITER2) issue_kv(j0 + 128, bi ^ 1);

        float s[16][4];
        #pragma unroll
        for (int nj = 0; nj < 16; nj++)
            #pragma unroll
            for (int r = 0; r < 4; r++) s[nj][r] = 0.f;
        #pragma unroll
        for (int kc = 0; kc < 4; kc++) {
            #pragma unroll
            for (int j = 0; j < 8; j++) {
                uint32_t bb[4];
                const uint32_t row = (uint32_t)((2 * j + nt) * 8 + (lane & 7)) * 128;
                ldsm4(bb, ksa[bi] + row + (((uint32_t)(kc * 32) + khB) ^ swl));
                mma_f16(s[2 * j],     qa[kc], &bb[0]);
                mma_f16(s[2 * j + 1], qa[kc], &bb[2]);
            }
        }

        if (j0 + 128 > SEQ) {
            #pragma unroll
            for (int nj = 0; nj < 16; nj++) {
                const int col = j0 + nj * 8 + c0;
                if (col >= SEQ)     { s[nj][0] = -1e30f; s[nj][2] = -1e30f; }
                if (col + 1 >= SEQ) { s[nj][1] = -1e30f; s[nj][3] = -1e30f; }
            }
        }

        float mx0 = -1e30f, mx1 = -1e30f;
        #pragma unroll
        for (int nj = 0; nj < 16; nj++) {
            mx0 = fmaxf(mx0, fmaxf(s[nj][0], s[nj][1]));
            mx1 = fmaxf(mx1, fmaxf(s[nj][2], s[nj][3]));
        }
        mx0 = fmaxf(mx0, __shfl_xor_sync(0xFFFFFFFFu, mx0, 1));
        mx0 = fmaxf(mx0, __shfl_xor_sync(0xFFFFFFFFu, mx0, 2));
        mx1 = fmaxf(mx1, __shfl_xor_sync(0xFFFFFFFFu, mx1, 1));
        mx1 = fmaxf(mx1, __shfl_xor_sync(0xFFFFFFFFu, mx1, 2));
        const float nm0 = fmaxf(m0, mx0), nm1 = fmaxf(m1, mx1);
        const float cr0 = exp2f(m0 - nm0), cr1 = exp2f(m1 - nm1);
        m0 = nm0; m1 = nm1;
        float rs0 = 0.f, rs1 = 0.f;
        #pragma unroll
        for (int nj = 0; nj < 16; nj++) {
            float p0 = exp2f(s[nj][0] - m0);
            float p1 = exp2f(s[nj][1] - m0);
            float p2 = exp2f(s[nj][2] - m1);
            float p3 = exp2f(s[nj][3] - m1);
            s[nj][0] = p0; s[nj][1] = p1; s[nj][2] = p2; s[nj][3] = p3;
            rs0 += p0 + p1;
            rs1 += p2 + p3;
        }
        rs0 += __shfl_xor_sync(0xFFFFFFFFu, rs0, 1);
        rs0 += __shfl_xor_sync(0xFFFFFFFFu, rs0, 2);
        rs1 += __shfl_xor_sync(0xFFFFFFFFu, rs1, 1);
        rs1 += __shfl_xor_sync(0xFFFFFFFFu, rs1, 2);
        l0 = l0 * cr0 + rs0;
        l1 = l1 * cr1 + rs1;
        #pragma unroll
        for (int nj = 0; nj < 8; nj++) {
            o[nj][0] *= cr0; o[nj][1] *= cr0;
            o[nj][2] *= cr1; o[nj][3] *= cr1;
        }

        #pragma unroll
        for (int kc = 0; kc < 8; kc++) {
            uint32_t pa[4];
            {
                __half2 t0 = __floats2half2_rn(s[2 * kc][0],     s[2 * kc][1]);
                __half2 t1 = __floats2half2_rn(s[2 * kc][2],     s[2 * kc][3]);
                __half2 t2 = __floats2half2_rn(s[2 * kc + 1][0], s[2 * kc + 1][1]);
                __half2 t3 = __floats2half2_rn(s[2 * kc + 1][2], s[2 * kc + 1][3]);
                pa[0] = *(uint32_t*)&t0; pa[1] = *(uint32_t*)&t1;
                pa[2] = *(uint32_t*)&t2; pa[3] = *(uint32_t*)&t3;
            }
            const uint32_t row = (uint32_t)(kc * 16 + rhalf * 8 + (lane & 7)) * 128;
            #pragma unroll
            for (int j = 0; j < 4; j++) {
                uint32_t vb[4];
                const uint32_t colb = 16u * (uint32_t)(2 * j + nt);
                ldsm4t(vb, vsa[bi] + row + (colb ^ swl));
                mma_f16(o[2 * j],     pa, &vb[0]);
                mma_f16(o[2 * j + 1], pa, &vb[2]);
            }
        }
    }

    #pragma unroll
    for (int half = 0; half < 2; half++) {
        const int qr = q0 + w * 16 + (lane >> 2) + half * 8;
        if (qr < SEQ) {
            const float inv = 1.0f / (half ? l1 : l0);
            const size_t mtok = (size_t)b * SEQ + qr;
            const uint32_t swr = ((uint32_t)(mtok & 7)) << 4;
            const size_t rowbase = ((size_t)h * MPAD + mtok) * 128;
            #pragma unroll
            for (int nj = 0; nj < 8; nj++) {
                const int d = nj * 8 + c0;
                __half2 h2 = __floats2half2_rn(o[nj][half * 2] * inv,
                                               o[nj][half * 2 + 1] * inv);
                *(uint32_t*)(oa + rowbase + (((uint32_t)(2 * d)) ^ swr)) = *(uint32_t*)&h2;
            }
        }
    }
}

// ---------------------------------------------------------------------------
// Launch
// ---------------------------------------------------------------------------
extern "C" void kernel_launch(void* const* d_in, const int* in_sizes, int n_in,
                              void* d_out, int out_size)
{
    const float* x      = (const float*)d_in[0];
    const float* ln1_g  = (const float*)d_in[1];
    const float* ln1_b  = (const float*)d_in[2];
    const float* w_qkv  = (const float*)d_in[3];
    const float* w_proj = (const float*)d_in[4];
    const float* b_proj = (const float*)d_in[5];
    const float* ln2_g  = (const float*)d_in[6];
    const float* ln2_b  = (const float*)d_in[7];
    const float* w_fc1  = (const float*)d_in[8];
    const float* b_fc1  = (const float*)d_in[9];
    const float* w_fc2  = (const float*)d_in[10];
    const float* b_fc2  = (const float*)d_in[11];
    float* out = (float*)d_out;

    __half *p_qkvh; float* p_x1;
    uint8_t *p_actA, *p_actB, *p_wqkv, *p_wproj, *p_wfc1, *p_wfc2;
    cudaGetSymbolAddress((void**)&p_qkvh,  g_qkvh);
    cudaGetSymbolAddress((void**)&p_x1,    g_x1);
    cudaGetSymbolAddress((void**)&p_actA,  g_actA);
    cudaGetSymbolAddress((void**)&p_actB,  g_actB);
    cudaGetSymbolAddress((void**)&p_wqkv,  g_wqkv);
    cudaGetSymbolAddress((void**)&p_wproj, g_wproj);
    cudaGetSymbolAddress((void**)&p_wfc1,  g_wfc1);
    cudaGetSymbolAddress((void**)&p_wfc2,  g_wfc2);

    cudaFuncSetAttribute(gemm_f16_ker<EPI_BIAS_RES>,
                         cudaFuncAttributeMaxDynamicSharedMemorySize, GEMM_SMEM);
    cudaFuncSetAttribute(gemm_f16_ker<EPI_GELU_H>,
                         cudaFuncAttributeMaxDynamicSharedMemorySize, GEMM_SMEM);
    cudaFuncSetAttribute(gemm_f16_ker<EPI_HALF>,
                         cudaFuncAttributeMaxDynamicSharedMemorySize, GEMM_SMEM);
    cudaFuncSetAttribute(attn_ker,
                         cudaFuncAttributeMaxDynamicSharedMemorySize, ATTN_SMEM);

    const int M = MTOK;
    const int MY = (M + 127) / 128;   // 289

    // 1) prep: LN1 + ALL weight conversions (one launch)
    prep_ker<<<PREP_BLKS, 256>>>(x, ln1_g, ln1_b, w_qkv, w_proj, w_fc1, w_fc2,
                                 p_actA, p_wqkv, p_wproj, p_wfc1, p_wfc2);
    // 2) qkv = h @ w_qkv -> fp16 row-major
    gemm_f16_ker<EPI_HALF><<<dim3(C_QKV / 256, MY), GTHREADS, GEMM_SMEM>>>(
        p_actA, p_wqkv, nullptr, nullptr, nullptr, p_qkvh, nullptr, M, C_QKV, C_EMB);
    // 3) flash attention -> fp16 acts A
    attn_ker<<<dim3((SEQ + 63) / 64, BATCH * NHEAD), 128, ATTN_SMEM>>>(p_qkvh, p_actA);
    // 4) x1 = x + att @ w_proj + b_proj
    gemm_f16_ker<EPI_BIAS_RES><<<dim3(C_EMB / 256, MY), GTHREADS, GEMM_SMEM>>>(
        p_actA, p_wproj, b_proj, x, p_x1, nullptr, nullptr, M, C_EMB, C_EMB);
    // 5) LN2 -> fp16 acts A
    ln_f16_ker<<<MTOK / 8, 256>>>(p_x1, ln2_g, ln2_b, p_actA);
    // 6) ff = gelu(h @ w_fc1 + b_fc1) -> fp16 acts B
    gemm_f16_ker<EPI_GELU_H><<<dim3(C_HID / 256, MY), GTHREADS, GEMM_SMEM>>>(
        p_actA, p_wfc1, b_fc1, nullptr, nullptr, nullptr, p_actB, M, C_HID, C_EMB);
    // 7) out = x1 + ff @ w_fc2 + b_fc2
    gemm_f16_ker<EPI_BIAS_RES><<<dim3(C_EMB / 256, MY), GTHREADS, GEMM_SMEM>>>(
        p_actB, p_wfc2, b_fc2, p_x1, out, nullptr, nullptr, M, C_EMB, C_HID);
}